// round 15
// baseline (speedup 1.0000x reference)
#include <cuda_runtime.h>
#include <cuda_fp16.h>
#include <cstdint>

// Problem constants
#define PP 16
#define EE 512
#define HH 512
#define NN 8192

// Tiling: block tile 64x128, 4 warps (2x2), warp tile 32x64, fp16 K-chunk = 64
#define BM 64
#define BN 128
#define BK 64           // half elements per chunk (= 128B per row)
#define NCHUNK 8        // 512 / 64
#define NPASS 4         // 512 / BN
#define STAGES 3
#define THREADS 128

#define ROWB 144                 // padded row stride in bytes (128B data + 16B pad)
#define ASTG (64 * ROWB)         // 9216 B per A stage
#define BSTG (128 * ROWB)        // 18432 B per B stage
#define OFF_B (STAGES * ASTG)
#define OFF_LOG (STAGES * ASTG + STAGES * BSTG)   // 82944
#define SMEM_DYN (OFF_LOG + 256 + 16)

// Device scratch (uint4 => 16B aligned). All values stored as fp16 (RN).
__device__ uint4 g_xh[(size_t)NN * EE / 8];         // x          [N][E]   half
__device__ uint4 g_w0h[(size_t)PP * EE * HH / 8];   // W0^T       [P][H][E] half (K-major)
__device__ uint4 g_w1h[(size_t)PP * HH * HH / 8];   // W1^T       [P][Ho][Hi] half
__device__ uint4 g_h0h[(size_t)PP * NN * HH / 8];   // h0         [P][N][H] half

__device__ __forceinline__ uint32_t h2u(__half2 v) {
    uint32_t u;
    memcpy(&u, &v, 4);
    return u;
}

// ---------------- Prologue kernels ----------------

// x fp32 -> fp16, 8 elements/thread
__global__ void cvt_x_kernel(const float4* __restrict__ x) {
    int j = blockIdx.x * blockDim.x + threadIdx.x;
    if (j >= NN * EE / 8) return;
    float4 a = x[2 * j], b = x[2 * j + 1];
    uint4 o;
    o.x = h2u(__floats2half2_rn(a.x, a.y));
    o.y = h2u(__floats2half2_rn(a.z, a.w));
    o.z = h2u(__floats2half2_rn(b.x, b.y));
    o.w = h2u(__floats2half2_rn(b.z, b.w));
    g_xh[j] = o;
}

// Transpose + fp16-convert W0 [P,E,H]->[P,H,E] and W1 [P,H,H]->[P,Ho,Hi]
__global__ void transpose_w_kernel(const float* __restrict__ W0,
                                   const float* __restrict__ W1) {
    __shared__ float t[32][33];
    const int z = blockIdx.z;  // 0..15: W0 p=z ; 16..31: W1 p=z-16
    const float* src = (z < 16) ? W0 + (size_t)z * EE * HH
                                : W1 + (size_t)(z - 16) * HH * HH;
    __half* dst = (z < 16) ? (__half*)g_w0h + (size_t)z * EE * HH
                           : (__half*)g_w1h + (size_t)(z - 16) * HH * HH;
    const int c0 = blockIdx.x * 32;  // src col (output-neuron n) base
    const int r0 = blockIdx.y * 32;  // src row (input-dim k) base
    const int tx = threadIdx.x, ty = threadIdx.y;
#pragma unroll
    for (int i = ty; i < 32; i += 8)
        t[i][tx] = src[(size_t)(r0 + i) * 512 + c0 + tx];
    __syncthreads();
#pragma unroll
    for (int i = ty; i < 32; i += 8)
        dst[(size_t)(c0 + i) * 512 + r0 + tx] = __float2half_rn(t[tx][i]);
}

// ---------------- Main kernel ----------------

__device__ __forceinline__ void mma16(float c[4], const uint32_t a[4],
                                      uint32_t b0, uint32_t b1) {
    asm volatile(
        "mma.sync.aligned.m16n8k16.row.col.f32.f16.f16.f32 "
        "{%0,%1,%2,%3}, {%4,%5,%6,%7}, {%8,%9}, {%0,%1,%2,%3};\n"
        : "+f"(c[0]), "+f"(c[1]), "+f"(c[2]), "+f"(c[3])
        : "r"(a[0]), "r"(a[1]), "r"(a[2]), "r"(a[3]), "r"(b0), "r"(b1));
}

#define LDSM_X4(r, addr)                                                     \
    asm volatile("ldmatrix.sync.aligned.m8n8.x4.shared.b16 {%0,%1,%2,%3}, [%4];" \
                 : "=r"((r)[0]), "=r"((r)[1]), "=r"((r)[2]), "=r"((r)[3])    \
                 : "r"(addr))

// cp.async one K-chunk: A [64 rows x 128B] + B [128 rows x 128B] into a stage.
__device__ __forceinline__ void issue_chunk(const __half* __restrict__ Ag,
                                            const __half* __restrict__ Bg,
                                            int kc, int stage, int tid,
                                            uint32_t sAu, uint32_t sBu) {
    const uint32_t aB = sAu + stage * ASTG;
    const uint32_t bB = sBu + stage * BSTG;
#pragma unroll
    for (int j = 0; j < 4; j++) {             // A: 512 x 16B over 128 threads
        int idx = tid + j * THREADS;
        int r = idx >> 3, c = idx & 7;
        uint32_t dst = aB + (uint32_t)(r * ROWB + c * 16);
        const __half* src = Ag + (size_t)r * 512 + kc * BK + c * 8;
        asm volatile("cp.async.cg.shared.global [%0], [%1], 16;\n" ::"r"(dst), "l"(src));
    }
#pragma unroll
    for (int j = 0; j < 8; j++) {             // B: 1024 x 16B
        int idx = tid + j * THREADS;
        int n = idx >> 3, c = idx & 7;
        uint32_t dst = bB + (uint32_t)(n * ROWB + c * 16);
        const __half* src = Bg + (size_t)n * 512 + kc * BK + c * 8;
        asm volatile("cp.async.cg.shared.global [%0], [%1], 16;\n" ::"r"(dst), "l"(src));
    }
    asm volatile("cp.async.commit_group;\n");
}

// MMA over one staged chunk: 4 k16-steps; A and B frags both via ldmatrix.x4.
__device__ __forceinline__ void compute_chunk(uint32_t aAddr, uint32_t bAddr,
                                              float acc[2][8][4]) {
#pragma unroll
    for (int kk = 0; kk < 4; kk++) {
        uint32_t af[2][4], bf[4][4];
#pragma unroll
        for (int mt = 0; mt < 2; mt++)
            LDSM_X4(af[mt], aAddr + mt * (16 * ROWB) + kk * 32);
#pragma unroll
        for (int bt = 0; bt < 4; bt++)
            LDSM_X4(bf[bt], bAddr + bt * (16 * ROWB) + kk * 32);
#pragma unroll
        for (int mt = 0; mt < 2; mt++)
#pragma unroll
            for (int bt = 0; bt < 4; bt++) {
                mma16(acc[mt][2 * bt],     af[mt], bf[bt][0], bf[bt][2]);
                mma16(acc[mt][2 * bt + 1], af[mt], bf[bt][1], bf[bt][3]);
            }
    }
}

// One pass: acc[64x128] += A[64x512] @ B[128x512]^T (both K-major, fp16)
__device__ __forceinline__ void gemm_pass(const __half* __restrict__ Ag,
                                          const __half* __restrict__ Bg,
                                          uint32_t sAu, uint32_t sBu,
                                          uint32_t aAddr0, uint32_t bAddr0,
                                          int tid, float acc[2][8][4]) {
#pragma unroll
    for (int mt = 0; mt < 2; mt++)
#pragma unroll
        for (int nt = 0; nt < 8; nt++)
#pragma unroll
            for (int c = 0; c < 4; c++) acc[mt][nt][c] = 0.f;

    __syncthreads();  // prior pass fully done with all stages
    issue_chunk(Ag, Bg, 0, 0, tid, sAu, sBu);
    issue_chunk(Ag, Bg, 1, 1, tid, sAu, sBu);

    int stage = 0;  // stage of chunk kc == kc % STAGES
    for (int kc = 0; kc < NCHUNK; kc++) {
        if (kc + 1 < NCHUNK) {
            asm volatile("cp.async.wait_group 1;\n" ::);
        } else {
            asm volatile("cp.async.wait_group 0;\n" ::);
        }
        __syncthreads();  // chunk kc resident; all warps done with stage being refilled
        if (kc + 2 < NCHUNK) {
            int s2 = stage + 2;
            if (s2 >= STAGES) s2 -= STAGES;
            issue_chunk(Ag, Bg, kc + 2, s2, tid, sAu, sBu);
        }
        compute_chunk(aAddr0 + stage * ASTG, bAddr0 + stage * BSTG, acc);
        stage = (stage == STAGES - 1) ? 0 : stage + 1;
    }
}

__global__ void __launch_bounds__(THREADS, 2)
mlp_kernel(const float* __restrict__ b0, const float* __restrict__ b1,
           const float* __restrict__ W2, const float* __restrict__ b2,
           float* __restrict__ out) {
    extern __shared__ char smemc[];
    uint32_t sAu;
    asm("{ .reg .u64 t; cvta.to.shared.u64 t, %1; cvt.u32.u64 %0, t; }"
        : "=r"(sAu) : "l"(smemc));
    const uint32_t sBu = sAu + OFF_B;
    float* sLog = (float*)(smemc + OFF_LOG);  // 64 floats

    const int tid = threadIdx.x;
    const int warp = tid >> 5, lane = tid & 31;
    const int wm = warp >> 1, wn = warp & 1;  // 2 x 2 warp grid
    const int qid = lane >> 2, qt = lane & 3;
    const int p = blockIdx.y;
    const int gm0 = blockIdx.x * BM;

    // ldmatrix per-lane bases (stage 0, mt/bt = 0, kk = 0)
    const uint32_t aAddr0 =
        sAu + (uint32_t)((wm * 32 + (lane & 15)) * ROWB + ((lane & 16) ? 16 : 0));
    const uint32_t bAddr0 =
        sBu + (uint32_t)((wn * 64 + (lane & 15)) * ROWB + ((lane & 16) ? 16 : 0));

    const __half* Ax = (const __half*)g_xh + (size_t)gm0 * EE;
    __half* hb = (__half*)g_h0h + ((size_t)p * NN + gm0) * HH;

    float acc[2][8][4];

    // ---------------- Layer 0: h0 = fp16(relu(x @ W0[p] + b0[p])) ----------------
    for (int pass = 0; pass < NPASS; pass++) {
        const int n0 = pass * BN;
        gemm_pass(Ax, (const __half*)g_w0h + (size_t)p * EE * HH + (size_t)n0 * EE,
                  sAu, sBu, aAddr0, bAddr0, tid, acc);

        const float* bptr = b0 + p * HH + n0;
#pragma unroll
        for (int nt = 0; nt < 8; nt++) {
            int col = wn * 64 + nt * 8 + qt * 2;
            float2 bb = *(const float2*)(bptr + col);
#pragma unroll
            for (int mt = 0; mt < 2; mt++) {
                int row = wm * 32 + mt * 16 + qid;
                __half2 o0 = __floats2half2_rn(fmaxf(acc[mt][nt][0] + bb.x, 0.f),
                                               fmaxf(acc[mt][nt][1] + bb.y, 0.f));
                __half2 o1 = __floats2half2_rn(fmaxf(acc[mt][nt][2] + bb.x, 0.f),
                                               fmaxf(acc[mt][nt][3] + bb.y, 0.f));
                *(__half2*)(hb + (size_t)row * HH + n0 + col) = o0;
                *(__half2*)(hb + (size_t)(row + 8) * HH + n0 + col) = o1;
            }
        }
    }

    __threadfence();   // h0 visible in L2 before cp.async.cg reads it
    __syncthreads();
    if (tid < BM) sLog[tid] = 0.f;  // ordered before atomics by gemm_pass's syncs

    // ------- Layer 1 + 2 fused: logit[n] = sum_h relu(h1[n,h]) * W2[p,h] -------
    float lpart[4];
#pragma unroll
    for (int i = 0; i < 4; i++) lpart[i] = 0.f;

    for (int pass = 0; pass < NPASS; pass++) {
        const int n0 = pass * BN;
        gemm_pass(hb, (const __half*)g_w1h + (size_t)p * HH * HH + (size_t)n0 * HH,
                  sAu, sBu, aAddr0, bAddr0, tid, acc);

        const float* bptr = b1 + p * HH + n0;
        const float* wptr = W2 + p * HH + n0;
#pragma unroll
        for (int nt = 0; nt < 8; nt++) {
            int col = wn * 64 + nt * 8 + qt * 2;
            float2 bb = *(const float2*)(bptr + col);
            float2 ww = *(const float2*)(wptr + col);
#pragma unroll
            for (int mt = 0; mt < 2; mt++) {
                float v0 = fmaxf(acc[mt][nt][0] + bb.x, 0.f);
                float v1 = fmaxf(acc[mt][nt][1] + bb.y, 0.f);
                float v2 = fmaxf(acc[mt][nt][2] + bb.x, 0.f);
                float v3 = fmaxf(acc[mt][nt][3] + bb.y, 0.f);
                lpart[2 * mt]     += v0 * ww.x + v1 * ww.y;  // row qid
                lpart[2 * mt + 1] += v2 * ww.x + v3 * ww.y;  // row qid+8
            }
        }
    }

    // Reduce across qt lanes (quad), then smem atomics across warps/nt
#pragma unroll
    for (int i = 0; i < 4; i++) {
        float v = lpart[i];
        v += __shfl_xor_sync(0xffffffffu, v, 1);
        v += __shfl_xor_sync(0xffffffffu, v, 2);
        if (qt == 0) {
            int row = wm * 32 + (i >> 1) * 16 + ((i & 1) ? 8 : 0) + qid;
            atomicAdd(&sLog[row], v);
        }
    }
    __syncthreads();

    if (tid < BM) {
        float logit = sLog[tid] + b2[p];
        out[(size_t)(gm0 + tid) * PP + p] = 1.f / (1.f + expf(-logit));
    }
}

extern "C" void kernel_launch(void* const* d_in, const int* in_sizes, int n_in,
                              void* d_out, int out_size) {
    const float* x  = (const float*)d_in[0];
    const float* W0 = (const float*)d_in[1];
    const float* b0 = (const float*)d_in[2];
    const float* W1 = (const float*)d_in[3];
    const float* b1 = (const float*)d_in[4];
    const float* W2 = (const float*)d_in[5];
    const float* b2 = (const float*)d_in[6];
    float* out = (float*)d_out;

    // Prologue: fp16-convert x; transpose+convert W0, W1 (K-major B operands)
    cvt_x_kernel<<<(NN * EE / 8) / 256, 256>>>((const float4*)x);
    transpose_w_kernel<<<dim3(16, 16, 32), dim3(32, 8)>>>(W0, W1);

    cudaFuncSetAttribute(mlp_kernel, cudaFuncAttributeMaxDynamicSharedMemorySize,
                         SMEM_DYN);
    mlp_kernel<<<dim3(NN / BM, PP), THREADS, SMEM_DYN>>>(b0, b1, W2, b2, out);
}

// round 16
// speedup vs baseline: 1.0760x; 1.0760x over previous
#include <cuda_runtime.h>
#include <cuda_fp16.h>
#include <cstdint>

// Problem constants
#define PP 16
#define EE 512
#define HH 512
#define NN 8192

// Tiling: block tile 128x128, 8 warps (4x2), warp tile 32x64, fp16 K-chunk = 64.
// A tile (128x512) is SMEM-RESIDENT per layer; only B streams through stages.
#define BM 128
#define BN 128
#define BK 64           // half elements per chunk (= 128B per row)
#define NCHUNK 8        // 512 / 64
#define NPASS 4         // 512 / BN
#define STAGES 3
#define THREADS 256

#define ROWA 1040                // A row stride: 1024B data + 16B pad (1040 % 128 == 16)
#define ROWB 144                 // B row stride: 128B data + 16B pad
#define ASZ (128 * ROWA)         // 133120 B resident A
#define BSTG (128 * ROWB)        // 18432 B per B stage
#define OFF_B ASZ
#define OFF_LOG (ASZ + STAGES * BSTG)   // 188416
#define SMEM_DYN (OFF_LOG + 512 + 16)

// Device scratch (uint4 => 16B aligned). All values stored as fp16 (RN).
__device__ uint4 g_xh[(size_t)NN * EE / 8];         // x          [N][E]   half
__device__ uint4 g_w0h[(size_t)PP * EE * HH / 8];   // W0^T       [P][H][E] half (K-major)
__device__ uint4 g_w1h[(size_t)PP * HH * HH / 8];   // W1^T       [P][Ho][Hi] half
__device__ uint4 g_h0h[(size_t)PP * NN * HH / 8];   // h0         [P][N][H] half

__device__ __forceinline__ uint32_t h2u(__half2 v) {
    uint32_t u;
    memcpy(&u, &v, 4);
    return u;
}

// ---------------- Prologue kernels ----------------

// x fp32 -> fp16, 8 elements/thread
__global__ void cvt_x_kernel(const float4* __restrict__ x) {
    int j = blockIdx.x * blockDim.x + threadIdx.x;
    if (j >= NN * EE / 8) return;
    float4 a = x[2 * j], b = x[2 * j + 1];
    uint4 o;
    o.x = h2u(__floats2half2_rn(a.x, a.y));
    o.y = h2u(__floats2half2_rn(a.z, a.w));
    o.z = h2u(__floats2half2_rn(b.x, b.y));
    o.w = h2u(__floats2half2_rn(b.z, b.w));
    g_xh[j] = o;
}

// Transpose + fp16-convert W0 [P,E,H]->[P,H,E] and W1 [P,H,H]->[P,Ho,Hi]
__global__ void transpose_w_kernel(const float* __restrict__ W0,
                                   const float* __restrict__ W1) {
    __shared__ float t[32][33];
    const int z = blockIdx.z;  // 0..15: W0 p=z ; 16..31: W1 p=z-16
    const float* src = (z < 16) ? W0 + (size_t)z * EE * HH
                                : W1 + (size_t)(z - 16) * HH * HH;
    __half* dst = (z < 16) ? (__half*)g_w0h + (size_t)z * EE * HH
                           : (__half*)g_w1h + (size_t)(z - 16) * HH * HH;
    const int c0 = blockIdx.x * 32;  // src col (output-neuron n) base
    const int r0 = blockIdx.y * 32;  // src row (input-dim k) base
    const int tx = threadIdx.x, ty = threadIdx.y;
#pragma unroll
    for (int i = ty; i < 32; i += 8)
        t[i][tx] = src[(size_t)(r0 + i) * 512 + c0 + tx];
    __syncthreads();
#pragma unroll
    for (int i = ty; i < 32; i += 8)
        dst[(size_t)(c0 + i) * 512 + r0 + tx] = __float2half_rn(t[tx][i]);
}

// ---------------- Main kernel ----------------

__device__ __forceinline__ void mma16(float c[4], const uint32_t a[4],
                                      uint32_t b0, uint32_t b1) {
    asm volatile(
        "mma.sync.aligned.m16n8k16.row.col.f32.f16.f16.f32 "
        "{%0,%1,%2,%3}, {%4,%5,%6,%7}, {%8,%9}, {%0,%1,%2,%3};\n"
        : "+f"(c[0]), "+f"(c[1]), "+f"(c[2]), "+f"(c[3])
        : "r"(a[0]), "r"(a[1]), "r"(a[2]), "r"(a[3]), "r"(b0), "r"(b1));
}

#define LDSM_X4(r, addr)                                                     \
    asm volatile("ldmatrix.sync.aligned.m8n8.x4.shared.b16 {%0,%1,%2,%3}, [%4];" \
                 : "=r"((r)[0]), "=r"((r)[1]), "=r"((r)[2]), "=r"((r)[3])    \
                 : "r"(addr))

// Load the full A tile [128 x 512 half] into resident SMEM (one commit group).
__device__ __forceinline__ void load_A(const __half* __restrict__ Ag,
                                       int tid, uint32_t sAu) {
#pragma unroll
    for (int j = 0; j < 32; j++) {            // 8192 x 16B over 256 threads
        int idx = tid + j * THREADS;
        int r = idx >> 6, u = idx & 63;
        uint32_t dst = sAu + (uint32_t)(r * ROWA + u * 16);
        const __half* src = Ag + (size_t)r * 512 + u * 8;
        asm volatile("cp.async.cg.shared.global [%0], [%1], 16;\n" ::"r"(dst), "l"(src));
    }
    asm volatile("cp.async.commit_group;\n");
}

// cp.async one B K-chunk [128 rows x 128B] into a stage.
__device__ __forceinline__ void issue_B(const __half* __restrict__ Bg,
                                        int kc, int stage, int tid, uint32_t sBu) {
    const uint32_t bB = sBu + stage * BSTG;
#pragma unroll
    for (int j = 0; j < 4; j++) {             // 1024 x 16B over 256 threads
        int idx = tid + j * THREADS;
        int n = idx >> 3, c = idx & 7;
        uint32_t dst = bB + (uint32_t)(n * ROWB + c * 16);
        const __half* src = Bg + (size_t)n * 512 + kc * BK + c * 8;
        asm volatile("cp.async.cg.shared.global [%0], [%1], 16;\n" ::"r"(dst), "l"(src));
    }
    asm volatile("cp.async.commit_group;\n");
}

// MMA over one chunk: A frags from resident buffer (column offset kc*128B),
// B frags from the stage. Warp tile 32x64: 2 A-LDSM + 4 B-LDSM per kk.
__device__ __forceinline__ void compute_chunk(uint32_t aAddr, uint32_t bAddr,
                                              float acc[2][8][4]) {
#pragma unroll
    for (int kk = 0; kk < 4; kk++) {
        uint32_t af[2][4], bf[4][4];
#pragma unroll
        for (int mt = 0; mt < 2; mt++)
            LDSM_X4(af[mt], aAddr + mt * (16 * ROWA) + kk * 32);
#pragma unroll
        for (int bt = 0; bt < 4; bt++)
            LDSM_X4(bf[bt], bAddr + bt * (16 * ROWB) + kk * 32);
#pragma unroll
        for (int mt = 0; mt < 2; mt++)
#pragma unroll
            for (int bt = 0; bt < 4; bt++) {
                mma16(acc[mt][2 * bt],     af[mt], bf[bt][0], bf[bt][2]);
                mma16(acc[mt][2 * bt + 1], af[mt], bf[bt][1], bf[bt][3]);
            }
    }
}

// One pass: acc[128x128] += A_resident[128x512] @ B[128x512]^T.
// Only B streams; the A commit-group (if first pass) retires with chunk 0's wait.
__device__ __forceinline__ void gemm_pass(const __half* __restrict__ Bg,
                                          uint32_t sAu, uint32_t sBu,
                                          uint32_t aAddr0, uint32_t bAddr0,
                                          int tid, float acc[2][8][4]) {
#pragma unroll
    for (int mt = 0; mt < 2; mt++)
#pragma unroll
        for (int nt = 0; nt < 8; nt++)
#pragma unroll
            for (int c = 0; c < 4; c++) acc[mt][nt][c] = 0.f;

    __syncthreads();  // prior pass fully done with all B stages
    issue_B(Bg, 0, 0, tid, sBu);
    issue_B(Bg, 1, 1, tid, sBu);

    int stage = 0;  // stage of chunk kc == kc % STAGES
    for (int kc = 0; kc < NCHUNK; kc++) {
        if (kc + 1 < NCHUNK) {
            asm volatile("cp.async.wait_group 1;\n" ::);
        } else {
            asm volatile("cp.async.wait_group 0;\n" ::);
        }
        __syncthreads();  // chunk kc resident; all warps done with stage being refilled
        if (kc + 2 < NCHUNK) {
            int s2 = stage + 2;
            if (s2 >= STAGES) s2 -= STAGES;
            issue_B(Bg, kc + 2, s2, tid, sBu);
        }
        compute_chunk(aAddr0 + kc * 128, bAddr0 + stage * BSTG, acc);
        stage = (stage == STAGES - 1) ? 0 : stage + 1;
    }
}

__global__ void __launch_bounds__(THREADS, 1)
mlp_kernel(const float* __restrict__ b0, const float* __restrict__ b1,
           const float* __restrict__ W2, const float* __restrict__ b2,
           float* __restrict__ out) {
    extern __shared__ char smemc[];
    uint32_t sAu;
    asm("{ .reg .u64 t; cvta.to.shared.u64 t, %1; cvt.u32.u64 %0, t; }"
        : "=r"(sAu) : "l"(smemc));
    const uint32_t sBu = sAu + OFF_B;
    float* sLog = (float*)(smemc + OFF_LOG);  // 128 floats

    const int tid = threadIdx.x;
    const int warp = tid >> 5, lane = tid & 31;
    const int wm = warp >> 1, wn = warp & 1;  // 4 x 2 warp grid
    const int qid = lane >> 2, qt = lane & 3;
    const int p = blockIdx.y;
    const int gm0 = blockIdx.x * BM;

    // ldmatrix per-lane bases (mt/bt = 0, kk = 0, kc = 0 / stage 0)
    const uint32_t aAddr0 =
        sAu + (uint32_t)((wm * 32 + (lane & 15)) * ROWA + ((lane & 16) ? 16 : 0));
    const uint32_t bAddr0 =
        sBu + (uint32_t)((wn * 64 + (lane & 15)) * ROWB + ((lane & 16) ? 16 : 0));

    const __half* Ax = (const __half*)g_xh + (size_t)gm0 * EE;
    __half* hb = (__half*)g_h0h + ((size_t)p * NN + gm0) * HH;

    float acc[2][8][4];

    // ---------------- Layer 0: h0 = fp16(relu(x @ W0[p] + b0[p])) ----------------
    load_A(Ax, tid, sAu);
    for (int pass = 0; pass < NPASS; pass++) {
        const int n0 = pass * BN;
        gemm_pass((const __half*)g_w0h + (size_t)p * EE * HH + (size_t)n0 * EE,
                  sAu, sBu, aAddr0, bAddr0, tid, acc);

        const float* bptr = b0 + p * HH + n0;
#pragma unroll
        for (int nt = 0; nt < 8; nt++) {
            int col = wn * 64 + nt * 8 + qt * 2;
            float2 bb = *(const float2*)(bptr + col);
#pragma unroll
            for (int mt = 0; mt < 2; mt++) {
                int row = wm * 32 + mt * 16 + qid;
                __half2 o0 = __floats2half2_rn(fmaxf(acc[mt][nt][0] + bb.x, 0.f),
                                               fmaxf(acc[mt][nt][1] + bb.y, 0.f));
                __half2 o1 = __floats2half2_rn(fmaxf(acc[mt][nt][2] + bb.x, 0.f),
                                               fmaxf(acc[mt][nt][3] + bb.y, 0.f));
                *(__half2*)(hb + (size_t)row * HH + n0 + col) = o0;
                *(__half2*)(hb + (size_t)(row + 8) * HH + n0 + col) = o1;
            }
        }
    }

    __threadfence();   // h0 visible in L2 before cp.async.cg reads it
    __syncthreads();   // also: all warps done reading resident A before overwrite

    // Reload resident A with h0 for layer 1
    load_A(hb, tid, sAu);
    if (tid < BM) sLog[tid] = 0.f;  // ordered before atomics by gemm_pass's syncs

    // ------- Layer 1 + 2 fused: logit[n] = sum_h relu(h1[n,h]) * W2[p,h] -------
    float lpart[4];
#pragma unroll
    for (int i = 0; i < 4; i++) lpart[i] = 0.f;

    for (int pass = 0; pass < NPASS; pass++) {
        const int n0 = pass * BN;
        gemm_pass((const __half*)g_w1h + (size_t)p * HH * HH + (size_t)n0 * HH,
                  sAu, sBu, aAddr0, bAddr0, tid, acc);

        const float* bptr = b1 + p * HH + n0;
        const float* wptr = W2 + p * HH + n0;
#pragma unroll
        for (int nt = 0; nt < 8; nt++) {
            int col = wn * 64 + nt * 8 + qt * 2;
            float2 bb = *(const float2*)(bptr + col);
            float2 ww = *(const float2*)(wptr + col);
#pragma unroll
            for (int mt = 0; mt < 2; mt++) {
                float v0 = fmaxf(acc[mt][nt][0] + bb.x, 0.f);
                float v1 = fmaxf(acc[mt][nt][1] + bb.y, 0.f);
                float v2 = fmaxf(acc[mt][nt][2] + bb.x, 0.f);
                float v3 = fmaxf(acc[mt][nt][3] + bb.y, 0.f);
                lpart[2 * mt]     += v0 * ww.x + v1 * ww.y;  // row qid
                lpart[2 * mt + 1] += v2 * ww.x + v3 * ww.y;  // row qid+8
            }
        }
    }

    // Reduce across qt lanes (quad), then smem atomics across warps/nt
#pragma unroll
    for (int i = 0; i < 4; i++) {
        float v = lpart[i];
        v += __shfl_xor_sync(0xffffffffu, v, 1);
        v += __shfl_xor_sync(0xffffffffu, v, 2);
        if (qt == 0) {
            int row = wm * 32 + ((i & 1) ? 8 : 0) + (i >> 1) * 16 + qid;
            atomicAdd(&sLog[row], v);
        }
    }
    __syncthreads();

    if (tid < BM) {
        float logit = sLog[tid] + b2[p];
        out[(size_t)(gm0 + tid) * PP + p] = 1.f / (1.f + expf(-logit));
    }
}

extern "C" void kernel_launch(void* const* d_in, const int* in_sizes, int n_in,
                              void* d_out, int out_size) {
    const float* x  = (const float*)d_in[0];
    const float* W0 = (const float*)d_in[1];
    const float* b0 = (const float*)d_in[2];
    const float* W1 = (const float*)d_in[3];
    const float* b1 = (const float*)d_in[4];
    const float* W2 = (const float*)d_in[5];
    const float* b2 = (const float*)d_in[6];
    float* out = (float*)d_out;

    // Prologue: fp16-convert x; transpose+convert W0, W1 (K-major B operands)
    cvt_x_kernel<<<(NN * EE / 8) / 256, 256>>>((const float4*)x);
    transpose_w_kernel<<<dim3(16, 16, 32), dim3(32, 8)>>>(W0, W1);

    cudaFuncSetAttribute(mlp_kernel, cudaFuncAttributeMaxDynamicSharedMemorySize,
                         SMEM_DYN);
    mlp_kernel<<<dim3(NN / BM, PP), THREADS, SMEM_DYN>>>(b0, b1, W2, b2, out);
}

// round 17
// speedup vs baseline: 1.3300x; 1.2361x over previous
#include <cuda_runtime.h>
#include <cuda_fp16.h>
#include <cstdint>

// Problem constants
#define PP 16
#define EE 512
#define HH 512
#define NN 8192

// Tiling: block tile 128x128, 4 warps (2x2), warp tile 64x64, fp16 K-chunk = 64.
// B kept NATIVE [k][n]; ldmatrix.trans produces the col-major fragments.
#define BM 128
#define BN 128
#define BK 64           // K elements per chunk
#define NCHUNK 8        // 512 / 64
#define NPASS 4         // 512 / BN
#define STAGES 3
#define THREADS 128

#define ROWA 144                 // A row stride bytes (128B data + 16B pad)
#define ROWB 272                 // B row stride bytes (256B data + 16B pad); 272%128==16
#define ASTG (128 * ROWA)        // 18432 B per A stage (128 m-rows x 64 k)
#define BSTG (64 * ROWB)         // 17408 B per B stage (64 k-rows x 128 n)
#define OFF_B (STAGES * ASTG)            // 55296
#define OFF_LOG (OFF_B + STAGES * BSTG)  // 107520
#define SMEM_DYN (OFF_LOG + 512 + 16)    // 108048 -> 2 CTAs/SM

// Device scratch (uint4 => 16B aligned). All values fp16 (RN), NATIVE layouts.
__device__ uint4 g_xh[(size_t)NN * EE / 8];         // x   [N][E]
__device__ uint4 g_w0h[(size_t)PP * EE * HH / 8];   // W0  [P][E][H]  (native [k][n])
__device__ uint4 g_w1h[(size_t)PP * HH * HH / 8];   // W1  [P][H][H]  (native [k][n])
__device__ uint4 g_h0h[(size_t)PP * NN * HH / 8];   // h0  [P][N][H]

__device__ __forceinline__ uint32_t h2u(__half2 v) {
    uint32_t u;
    memcpy(&u, &v, 4);
    return u;
}

// ---------------- Prologue: one elementwise fp32->fp16 kernel ----------------
// x, W0, W1 all have exactly NN*EE == PP*EE*HH == 4194304 elements.
__global__ void cvt_all_kernel(const float4* __restrict__ x,
                               const float4* __restrict__ W0,
                               const float4* __restrict__ W1) {
    int j = blockIdx.x * blockDim.x + threadIdx.x;
    if (j >= NN * EE / 8) return;
    float4 a, b;
    uint4 o;
    a = x[2 * j]; b = x[2 * j + 1];
    o.x = h2u(__floats2half2_rn(a.x, a.y));
    o.y = h2u(__floats2half2_rn(a.z, a.w));
    o.z = h2u(__floats2half2_rn(b.x, b.y));
    o.w = h2u(__floats2half2_rn(b.z, b.w));
    g_xh[j] = o;
    a = W0[2 * j]; b = W0[2 * j + 1];
    o.x = h2u(__floats2half2_rn(a.x, a.y));
    o.y = h2u(__floats2half2_rn(a.z, a.w));
    o.z = h2u(__floats2half2_rn(b.x, b.y));
    o.w = h2u(__floats2half2_rn(b.z, b.w));
    g_w0h[j] = o;
    a = W1[2 * j]; b = W1[2 * j + 1];
    o.x = h2u(__floats2half2_rn(a.x, a.y));
    o.y = h2u(__floats2half2_rn(a.z, a.w));
    o.z = h2u(__floats2half2_rn(b.x, b.y));
    o.w = h2u(__floats2half2_rn(b.z, b.w));
    g_w1h[j] = o;
}

// ---------------- Main kernel ----------------

__device__ __forceinline__ void mma16(float c[4], const uint32_t a[4],
                                      uint32_t b0, uint32_t b1) {
    asm volatile(
        "mma.sync.aligned.m16n8k16.row.col.f32.f16.f16.f32 "
        "{%0,%1,%2,%3}, {%4,%5,%6,%7}, {%8,%9}, {%0,%1,%2,%3};\n"
        : "+f"(c[0]), "+f"(c[1]), "+f"(c[2]), "+f"(c[3])
        : "r"(a[0]), "r"(a[1]), "r"(a[2]), "r"(a[3]), "r"(b0), "r"(b1));
}

#define LDSM_X4(r, addr)                                                     \
    asm volatile("ldmatrix.sync.aligned.m8n8.x4.shared.b16 {%0,%1,%2,%3}, [%4];" \
                 : "=r"((r)[0]), "=r"((r)[1]), "=r"((r)[2]), "=r"((r)[3])    \
                 : "r"(addr))

// Transposing load for native [k][n] B tiles -> col-major fragments.
// Matrices: r0=(k0-7,n0-7) r1=(k8-15,n0-7) r2=(k0-7,n8-15) r3=(k8-15,n8-15);
// after .trans these are exactly {b0_lo, b1_lo, b0_hi, b1_hi}.
#define LDSM_X4_T(r, addr)                                                   \
    asm volatile("ldmatrix.sync.aligned.m8n8.x4.trans.shared.b16 {%0,%1,%2,%3}, [%4];" \
                 : "=r"((r)[0]), "=r"((r)[1]), "=r"((r)[2]), "=r"((r)[3])    \
                 : "r"(addr))

// cp.async one K-chunk: A [128 m-rows x 128B] + B [64 k-rows x 256B] into a stage.
__device__ __forceinline__ void issue_chunk(const __half* __restrict__ Ag,
                                            const __half* __restrict__ Bg,
                                            int kc, int stage, int tid,
                                            uint32_t sAu, uint32_t sBu) {
    const uint32_t aB = sAu + stage * ASTG;
    const uint32_t bB = sBu + stage * BSTG;
#pragma unroll
    for (int j = 0; j < 8; j++) {             // A: 1024 x 16B over 128 threads
        int idx = tid + j * THREADS;
        int r = idx >> 3, c = idx & 7;
        uint32_t dst = aB + (uint32_t)(r * ROWA + c * 16);
        const __half* src = Ag + (size_t)r * 512 + kc * BK + c * 8;
        asm volatile("cp.async.cg.shared.global [%0], [%1], 16;\n" ::"r"(dst), "l"(src));
    }
#pragma unroll
    for (int j = 0; j < 8; j++) {             // B: 64 rows x 16 uint4 (native [k][n])
        int idx = tid + j * THREADS;
        int r = idx >> 4, c = idx & 15;
        uint32_t dst = bB + (uint32_t)(r * ROWB + c * 16);
        const __half* src = Bg + (size_t)(kc * BK + r) * 512 + c * 8;
        asm volatile("cp.async.cg.shared.global [%0], [%1], 16;\n" ::"r"(dst), "l"(src));
    }
    asm volatile("cp.async.commit_group;\n");
}

// MMA over one staged chunk: 4 k16-steps; A via ldmatrix, B via ldmatrix.trans.
__device__ __forceinline__ void compute_chunk(uint32_t aAddr, uint32_t bAddr,
                                              float acc[4][8][4]) {
#pragma unroll
    for (int kk = 0; kk < 4; kk++) {
        uint32_t af[4][4], bf[4][4];
#pragma unroll
        for (int mt = 0; mt < 4; mt++)
            LDSM_X4(af[mt], aAddr + mt * (16 * ROWA) + kk * 32);
#pragma unroll
        for (int bt = 0; bt < 4; bt++)
            LDSM_X4_T(bf[bt], bAddr + kk * (16 * ROWB) + bt * 32);
#pragma unroll
        for (int mt = 0; mt < 4; mt++)
#pragma unroll
            for (int bt = 0; bt < 4; bt++) {
                mma16(acc[mt][2 * bt],     af[mt], bf[bt][0], bf[bt][1]);
                mma16(acc[mt][2 * bt + 1], af[mt], bf[bt][2], bf[bt][3]);
            }
    }
}

// One pass: acc[128x128] += A[128x512] @ W[512x(n0:n0+128)]  (B native [k][n])
__device__ __forceinline__ void gemm_pass(const __half* __restrict__ Ag,
                                          const __half* __restrict__ Bg,
                                          uint32_t sAu, uint32_t sBu,
                                          uint32_t aAddr0, uint32_t bAddr0,
                                          int tid, float acc[4][8][4]) {
#pragma unroll
    for (int mt = 0; mt < 4; mt++)
#pragma unroll
        for (int nt = 0; nt < 8; nt++)
#pragma unroll
            for (int c = 0; c < 4; c++) acc[mt][nt][c] = 0.f;

    __syncthreads();  // prior pass fully done with all stages
    issue_chunk(Ag, Bg, 0, 0, tid, sAu, sBu);
    issue_chunk(Ag, Bg, 1, 1, tid, sAu, sBu);

    int stage = 0;  // stage of chunk kc == kc % STAGES
    for (int kc = 0; kc < NCHUNK; kc++) {
        if (kc + 1 < NCHUNK) {
            asm volatile("cp.async.wait_group 1;\n" ::);
        } else {
            asm volatile("cp.async.wait_group 0;\n" ::);
        }
        __syncthreads();  // chunk kc resident; all warps done with stage being refilled
        if (kc + 2 < NCHUNK) {
            int s2 = stage + 2;
            if (s2 >= STAGES) s2 -= STAGES;
            issue_chunk(Ag, Bg, kc + 2, s2, tid, sAu, sBu);
        }
        compute_chunk(aAddr0 + stage * ASTG, bAddr0 + stage * BSTG, acc);
        stage = (stage == STAGES - 1) ? 0 : stage + 1;
    }
}

__global__ void __launch_bounds__(THREADS, 2)
mlp_kernel(const float* __restrict__ b0, const float* __restrict__ b1,
           const float* __restrict__ W2, const float* __restrict__ b2,
           float* __restrict__ out) {
    extern __shared__ char smemc[];
    uint32_t sAu;
    asm("{ .reg .u64 t; cvta.to.shared.u64 t, %1; cvt.u32.u64 %0, t; }"
        : "=r"(sAu) : "l"(smemc));
    const uint32_t sBu = sAu + OFF_B;
    float* sLog = (float*)(smemc + OFF_LOG);  // 128 floats

    const int tid = threadIdx.x;
    const int warp = tid >> 5, lane = tid & 31;
    const int wm = warp >> 1, wn = warp & 1;  // 2 x 2 warp grid
    const int qid = lane >> 2, qt = lane & 3;
    const int p = blockIdx.y;
    const int gm0 = blockIdx.x * BM;

    // Per-lane ldmatrix bases (stage 0, mt/bt = 0, kk = 0)
    const uint32_t aAddr0 =
        sAu + (uint32_t)((wm * 64 + (lane & 15)) * ROWA + ((lane & 16) ? 16 : 0));
    // B (trans): lanes 0-15 -> k-rows 0-15 at n-offset 0; lanes 16-31 -> same k, n+8
    const uint32_t bAddr0 =
        sBu + (uint32_t)((lane & 15) * ROWB + (wn * 64 + (lane >> 4) * 8) * 2);

    const __half* Ax = (const __half*)g_xh + (size_t)gm0 * EE;
    __half* hb = (__half*)g_h0h + ((size_t)p * NN + gm0) * HH;

    float acc[4][8][4];

    // ---------------- Layer 0: h0 = fp16(relu(x @ W0[p] + b0[p])) ----------------
    for (int pass = 0; pass < NPASS; pass++) {
        const int n0 = pass * BN;
        gemm_pass(Ax, (const __half*)g_w0h + (size_t)p * EE * HH + n0,
                  sAu, sBu, aAddr0, bAddr0, tid, acc);

        const float* bptr = b0 + p * HH + n0;
#pragma unroll
        for (int nt = 0; nt < 8; nt++) {
            int col = wn * 64 + nt * 8 + qt * 2;
            float2 bb = *(const float2*)(bptr + col);
#pragma unroll
            for (int mt = 0; mt < 4; mt++) {
                int row = wm * 64 + mt * 16 + qid;
                __half2 o0 = __floats2half2_rn(fmaxf(acc[mt][nt][0] + bb.x, 0.f),
                                               fmaxf(acc[mt][nt][1] + bb.y, 0.f));
                __half2 o1 = __floats2half2_rn(fmaxf(acc[mt][nt][2] + bb.x, 0.f),
                                               fmaxf(acc[mt][nt][3] + bb.y, 0.f));
                *(__half2*)(hb + (size_t)row * HH + n0 + col) = o0;
                *(__half2*)(hb + (size_t)(row + 8) * HH + n0 + col) = o1;
            }
        }
    }

    __threadfence();   // h0 visible in L2 before cp.async.cg reads it
    __syncthreads();
    if (tid < BM) sLog[tid] = 0.f;  // ordered before atomics by gemm_pass's syncs

    // ------- Layer 1 + 2 fused: logit[n] = sum_h relu(h1[n,h]) * W2[p,h] -------
    float lpart[8];
#pragma unroll
    for (int i = 0; i < 8; i++) lpart[i] = 0.f;

    for (int pass = 0; pass < NPASS; pass++) {
        const int n0 = pass * BN;
        gemm_pass(hb, (const __half*)g_w1h + (size_t)p * HH * HH + n0,
                  sAu, sBu, aAddr0, bAddr0, tid, acc);

        const float* bptr = b1 + p * HH + n0;
        const float* wptr = W2 + p * HH + n0;
#pragma unroll
        for (int nt = 0; nt < 8; nt++) {
            int col = wn * 64 + nt * 8 + qt * 2;
            float2 bb = *(const float2*)(bptr + col);
            float2 ww = *(const float2*)(wptr + col);
#pragma unroll
            for (int mt = 0; mt < 4; mt++) {
                float v0 = fmaxf(acc[mt][nt][0] + bb.x, 0.f);
                float v1 = fmaxf(acc[mt][nt][1] + bb.y, 0.f);
                float v2 = fmaxf(acc[mt][nt][2] + bb.x, 0.f);
                float v3 = fmaxf(acc[mt][nt][3] + bb.y, 0.f);
                lpart[2 * mt]     += v0 * ww.x + v1 * ww.y;  // row qid
                lpart[2 * mt + 1] += v2 * ww.x + v3 * ww.y;  // row qid+8
            }
        }
    }

    // Reduce across qt lanes (quad), then smem atomics across warps/nt
#pragma unroll
    for (int i = 0; i < 8; i++) {
        float v = lpart[i];
        v += __shfl_xor_sync(0xffffffffu, v, 1);
        v += __shfl_xor_sync(0xffffffffu, v, 2);
        if (qt == 0) {
            int row = wm * 64 + (i >> 1) * 16 + ((i & 1) ? 8 : 0) + qid;
            atomicAdd(&sLog[row], v);
        }
    }
    __syncthreads();

    if (tid < BM) {
        float logit = sLog[tid] + b2[p];
        out[(size_t)(gm0 + tid) * PP + p] = 1.f / (1.f + expf(-logit));
    }
}

extern "C" void kernel_launch(void* const* d_in, const int* in_sizes, int n_in,
                              void* d_out, int out_size) {
    const float* x  = (const float*)d_in[0];
    const float* W0 = (const float*)d_in[1];
    const float* b0 = (const float*)d_in[2];
    const float* W1 = (const float*)d_in[3];
    const float* b1 = (const float*)d_in[4];
    const float* W2 = (const float*)d_in[5];
    const float* b2 = (const float*)d_in[6];
    float* out = (float*)d_out;

    // Prologue: single fused elementwise fp32->fp16 conversion (no transpose)
    cvt_all_kernel<<<(NN * EE / 8) / 256, 256>>>((const float4*)x, (const float4*)W0,
                                                 (const float4*)W1);

    cudaFuncSetAttribute(mlp_kernel, cudaFuncAttributeMaxDynamicSharedMemorySize,
                         SMEM_DYN);
    mlp_kernel<<<dim3(NN / BM, PP), THREADS, SMEM_DYN>>>(b0, b1, W2, b2, out);
}